// round 14
// baseline (speedup 1.0000x reference)
#include <cuda_runtime.h>
#include <cuda_bf16.h>
#include <cstdint>

#define NPROMPT 50
#define MPAD 64              // padded prompt count (GEMM M)
#define D 768
#define KC 64                // k per chunk
#define NCHUNK (D / KC)      // 12
#define NTILE 128            // pe rows per CTA tile (GEMM N)
#define NVEC 201728          // 1024 * 197
#define NBLK (NVEC / NTILE)  // 1576 tiles
#define EPSV 1e-6f
#define NTHREADS 512
#define GRID 296             // 148 SMs x 2 CTAs (persistent)

#define LDA 72               // A-chunk smem row stride (halves)
#define LDB 72               // B-chunk smem row stride (halves)

__device__ __align__(16) __nv_bfloat16 g_B[MPAD * D];
__device__ float g_ns[MPAD];
__device__ double g_acc;
__device__ int g_tile;

// ---------------------------------------------------------------- prep ----
__global__ void prep_kernel(const float* __restrict__ src) {
    int p = blockIdx.x, tid = threadIdx.x;
    float local = 0.f;
    for (int k = tid; k < D; k += blockDim.x) {
        float v = (p < NPROMPT) ? src[p * D + k] + EPSV : 0.f;
        g_B[p * D + k] = __float2bfloat16(v);
        local += v * v;
    }
    __shared__ float sh[256];
    sh[tid] = local;
    __syncthreads();
    for (int s = 128; s > 0; s >>= 1) {
        if (tid < s) sh[tid] += sh[tid + s];
        __syncthreads();
    }
    if (tid == 0) {
        g_ns[p] = sh[0];
        if (p == 0) { g_acc = 0.0; g_tile = 0; }
    }
}

// ------------------------------------------------------------- helpers ----
__device__ __forceinline__ uint32_t pack_bf2(float lo, float hi) {
    __nv_bfloat162 t = __floats2bfloat162_rn(lo, hi);
    return *reinterpret_cast<uint32_t*>(&t);
}

__device__ __forceinline__ void ldsm4(uint32_t& r0, uint32_t& r1, uint32_t& r2,
                                      uint32_t& r3, uint32_t addr) {
    asm volatile("ldmatrix.sync.aligned.m8n8.x4.shared.b16 {%0,%1,%2,%3}, [%4];\n"
                 : "=r"(r0), "=r"(r1), "=r"(r2), "=r"(r3)
                 : "r"(addr));
}

__device__ __forceinline__ void mma16816(float* c, uint32_t a0, uint32_t a1,
                                         uint32_t a2, uint32_t a3, uint32_t b0,
                                         uint32_t b1) {
    asm volatile(
        "mma.sync.aligned.m16n8k16.row.col.f32.bf16.bf16.f32 "
        "{%0,%1,%2,%3}, {%4,%5,%6,%7}, {%8,%9}, {%0,%1,%2,%3};\n"
        : "+f"(c[0]), "+f"(c[1]), "+f"(c[2]), "+f"(c[3])
        : "r"(a0), "r"(a1), "r"(a2), "r"(a3), "r"(b0), "r"(b1));
}

__device__ __forceinline__ void cp_async16(uint32_t dst, const void* src) {
    asm volatile("cp.async.cg.shared.global [%0], [%1], 16;" ::"r"(dst),
                 "l"(src)
                 : "memory");
}
#define CP_COMMIT() asm volatile("cp.async.commit_group;" ::: "memory")
#define CP_WAIT0() asm volatile("cp.async.wait_group 0;" ::: "memory")

// ---------------------------------------------------------------- main ----
constexpr int SA_HALVES = 2 * MPAD * LDA;
constexpr int SB_HALVES = 2 * NTILE * LDB;
constexpr int SMEM_BYTES =
    (SA_HALVES + SB_HALVES) * 2 + (NTILE + MPAD + 16 + 4) * 4;

__global__ void __launch_bounds__(NTHREADS, 2)
dist_kernel(const float* __restrict__ pe) {
    extern __shared__ char smem_raw[];
    __nv_bfloat16* sA = (__nv_bfloat16*)smem_raw;
    __nv_bfloat16* sB = sA + SA_HALVES;
    float* sNpe = (float*)(sB + SB_HALVES);
    float* sNs = sNpe + NTILE;
    float* sRed = sNs + MPAD;
    int* sTile = (int*)(sRed + 16);

    const int tid = threadIdx.x;
    const int warp = tid >> 5, lane = tid & 31;
    const int m_base = (warp >> 2) * 16;  // 4 m-groups over M=64
    const int n_base = (warp & 3) * 32;   // 4 n-groups over N=128

    if (tid < MPAD) sNs[tid] = g_ns[tid];

    // B loader mapping (coalesced): thread's j-th load at q*16B + j*64B
    const int r0 = tid >> 2;           // 0..127
    const int q4 = tid & 3;            // 16B sub-slot
    const size_t rowOff = (size_t)r0 * D + q4 * 4;

    // A (cp.async): 8 threads per prompt row; thread copies 1 x 16B slot
    const int ra = tid >> 3;
    const int qa = tid & 7;
    const uint32_t sA_u = (uint32_t)__cvta_generic_to_shared(sA);
    const uint32_t sB_u = (uint32_t)__cvta_generic_to_shared(sB);
    const uint32_t aDst = sA_u + (uint32_t)(ra * LDA + qa * 8) * 2;
    const __nv_bfloat16* aSrc = g_B + ra * D + qa * 8;

    const uint32_t a_off =
        (uint32_t)((m_base + (lane & 15)) * LDA + (lane >> 4) * 8) * 2;
    const uint32_t b_row = (uint32_t)(n_base + ((lane >> 4) & 1) * 8 + (lane & 7));
    const uint32_t b_k = ((lane >> 3) & 1) * 8;
    const int er = lane >> 2, ec2 = (lane & 3) * 2;

    float4 v[4];
    float lsum = 0.f;

#define CPA_A(ck, buf)                                                        \
    {                                                                         \
        cp_async16(aDst + (uint32_t)((buf)*MPAD * LDA * 2),                   \
                   aSrc + (ck)*KC);                                           \
        CP_COMMIT();                                                          \
    }
#define LDG_B(ck)                                                             \
    {                                                                         \
        const float* p = rowPtr + (ck)*KC;                                    \
        _Pragma("unroll") for (int j = 0; j < 4; ++j)                         \
            v[j] = *(const float4*)(p + j * 16);                              \
    }
#define STS_B(buf)                                                            \
    {                                                                         \
        __nv_bfloat16* dst = sB + (buf)*NTILE * LDB + r0 * LDB + q4 * 4;      \
        _Pragma("unroll") for (int j = 0; j < 4; ++j) {                       \
            nacc += v[j].x * v[j].x + v[j].y * v[j].y + v[j].z * v[j].z +     \
                    v[j].w * v[j].w;                                          \
            uint2 u;                                                          \
            u.x = pack_bf2(v[j].x, v[j].y);                                   \
            u.y = pack_bf2(v[j].z, v[j].w);                                   \
            *(uint2*)(dst + j * 16) = u;                                      \
        }                                                                     \
    }
#define STEP(s, abase, bbase)                                                 \
    {                                                                         \
        uint32_t a0, a1, a2, a3;                                              \
        ldsm4(a0, a1, a2, a3, (abase) + a_off + (s)*16 * 2);                  \
        _Pragma("unroll") for (int jj = 0; jj < 2; ++jj) {                    \
            uint32_t b0, b1, b2, b3;                                          \
            uint32_t baddr =                                                  \
                (bbase) + ((b_row + jj * 16) * LDB + (s)*16 + b_k) * 2;       \
            ldsm4(b0, b1, b2, b3, baddr);                                     \
            mma16816(acc[2 * jj], a0, a1, a2, a3, b0, b1);                    \
            mma16816(acc[2 * jj + 1], a0, a1, a2, a3, b2, b3);                \
        }                                                                     \
    }

    // ================= persistent tile loop =================
    for (;;) {
        if (tid == 0) *sTile = atomicAdd(&g_tile, 1);
        __syncthreads();
        const int t = *sTile;
        if (t >= NBLK) break;

        const float* rowPtr = pe + (size_t)t * NTILE * D + rowOff;
        float nacc = 0.f;
        float acc[4][4];
#pragma unroll
        for (int j = 0; j < 4; ++j)
#pragma unroll
            for (int q = 0; q < 4; ++q) acc[j][q] = 0.f;

        // prologue: chunk 0 -> buffer 0
        CPA_A(0, 0);
        LDG_B(0);
        STS_B(0);
        CP_WAIT0();
        __syncthreads();

#pragma unroll 1
        for (int it = 0; it < NCHUNK; ++it) {
            const uint32_t abase = sA_u + (uint32_t)((it & 1) * MPAD * LDA * 2);
            const uint32_t bbase = sB_u + (uint32_t)((it & 1) * NTILE * LDB * 2);
            const bool dl = (it + 1) < NCHUNK;
            const int nb = (it + 1) & 1;

            if (dl) { LDG_B(it + 1); CPA_A(it + 1, nb); }
            STEP(0, abase, bbase);
            STEP(1, abase, bbase);
            STEP(2, abase, bbase);
            STEP(3, abase, bbase);
            if (dl) { STS_B(nb); CP_WAIT0(); }
            __syncthreads();
        }

        // |pe|^2 per row: combine the four quarter-row partials
        nacc += __shfl_xor_sync(0xffffffffu, nacc, 1);
        nacc += __shfl_xor_sync(0xffffffffu, nacc, 2);
        if ((tid & 3) == 0) sNpe[r0] = nacc;
        __syncthreads();

        // epilogue: d = sqrt(|s'|^2 + |pe|^2 - 2 dot), mask prompts >= 50
#pragma unroll
        for (int j = 0; j < 4; ++j) {
            int n = n_base + j * 8 + ec2;
            float np0 = sNpe[n], np1 = sNpe[n + 1];
            int m0 = m_base + er;
            if (m0 < NPROMPT) {
                float ns0 = sNs[m0];
                lsum += sqrtf(fmaxf(ns0 + np0 - 2.f * acc[j][0], 0.f));
                lsum += sqrtf(fmaxf(ns0 + np1 - 2.f * acc[j][1], 0.f));
            }
            int m1 = m0 + 8;
            if (m1 < NPROMPT) {
                float ns1 = sNs[m1];
                lsum += sqrtf(fmaxf(ns1 + np0 - 2.f * acc[j][2], 0.f));
                lsum += sqrtf(fmaxf(ns1 + np1 - 2.f * acc[j][3], 0.f));
            }
        }
        // next iteration's tile-fetch __syncthreads orders sNpe reuse
    }

    // ---- block reduction of lsum across all tiles this CTA processed
#pragma unroll
    for (int o = 16; o > 0; o >>= 1)
        lsum += __shfl_xor_sync(0xffffffffu, lsum, o);
    if (lane == 0) sRed[warp] = lsum;
    __syncthreads();
    if (warp == 0) {
        float sv = (lane < 16) ? sRed[lane] : 0.f;
#pragma unroll
        for (int o = 8; o > 0; o >>= 1)
            sv += __shfl_xor_sync(0xffffffffu, sv, o);
        if (lane == 0) atomicAdd(&g_acc, (double)sv);
    }
}

// -------------------------------------------------------------- finish ----
__global__ void finish_kernel(float* out) {
    out[0] = (float)(g_acc * (1.0 / ((double)NPROMPT * 197.0 * 1024.0)));
}

// -------------------------------------------------------------- launch ----
extern "C" void kernel_launch(void* const* d_in, const int* in_sizes, int n_in,
                              void* d_out, int out_size) {
    const float* src = (const float*)d_in[0];  // source_prompt [50,768]
    const float* pe = (const float*)d_in[1];   // patch_embeds [1024,197,768]
    float* out = (float*)d_out;

    cudaFuncSetAttribute(dist_kernel, cudaFuncAttributeMaxDynamicSharedMemorySize,
                         SMEM_BYTES);

    prep_kernel<<<MPAD, 256>>>(src);
    dist_kernel<<<GRID, NTHREADS, SMEM_BYTES>>>(pe);
    finish_kernel<<<1, 1>>>(out);
}

// round 15
// speedup vs baseline: 1.0004x; 1.0004x over previous
#include <cuda_runtime.h>
#include <cuda_bf16.h>
#include <cstdint>

#define NPROMPT 50
#define MPAD 64              // padded prompt count (GEMM M)
#define D 768
#define KC 64                // k per chunk
#define NCHUNK (D / KC)      // 12
#define NTILE 128            // pe rows per CTA tile (GEMM N)
#define NVEC 201728          // 1024 * 197
#define NBLK (NVEC / NTILE)  // 1576 tiles
#define EPSV 1e-6f
#define NTHREADS 512
#define GRID 296             // 148 SMs x 2 CTAs (persistent)

#define LDA 72               // A-chunk smem row stride (halves)
#define LDB 72               // B-chunk smem row stride (halves)

__device__ __align__(16) __nv_bfloat16 g_B[MPAD * D];
__device__ float g_ns[MPAD];
__device__ double g_acc;
__device__ int g_tile;

// ---------------------------------------------------------------- prep ----
__global__ void prep_kernel(const float* __restrict__ src) {
    int p = blockIdx.x, tid = threadIdx.x;
    float local = 0.f;
    for (int k = tid; k < D; k += blockDim.x) {
        float v = (p < NPROMPT) ? src[p * D + k] + EPSV : 0.f;
        g_B[p * D + k] = __float2bfloat16(v);
        local += v * v;
    }
    __shared__ float sh[256];
    sh[tid] = local;
    __syncthreads();
    for (int s = 128; s > 0; s >>= 1) {
        if (tid < s) sh[tid] += sh[tid + s];
        __syncthreads();
    }
    if (tid == 0) {
        g_ns[p] = sh[0];
        if (p == 0) { g_acc = 0.0; g_tile = 0; }
    }
}

// ------------------------------------------------------------- helpers ----
__device__ __forceinline__ uint32_t pack_bf2(float lo, float hi) {
    __nv_bfloat162 t = __floats2bfloat162_rn(lo, hi);
    return *reinterpret_cast<uint32_t*>(&t);
}

__device__ __forceinline__ void ldsm4(uint32_t& r0, uint32_t& r1, uint32_t& r2,
                                      uint32_t& r3, uint32_t addr) {
    asm volatile("ldmatrix.sync.aligned.m8n8.x4.shared.b16 {%0,%1,%2,%3}, [%4];\n"
                 : "=r"(r0), "=r"(r1), "=r"(r2), "=r"(r3)
                 : "r"(addr));
}

__device__ __forceinline__ void mma16816(float* c, uint32_t a0, uint32_t a1,
                                         uint32_t a2, uint32_t a3, uint32_t b0,
                                         uint32_t b1) {
    asm volatile(
        "mma.sync.aligned.m16n8k16.row.col.f32.bf16.bf16.f32 "
        "{%0,%1,%2,%3}, {%4,%5,%6,%7}, {%8,%9}, {%0,%1,%2,%3};\n"
        : "+f"(c[0]), "+f"(c[1]), "+f"(c[2]), "+f"(c[3])
        : "r"(a0), "r"(a1), "r"(a2), "r"(a3), "r"(b0), "r"(b1));
}

__device__ __forceinline__ void cp_async16(uint32_t dst, const void* src) {
    asm volatile("cp.async.cg.shared.global [%0], [%1], 16;" ::"r"(dst),
                 "l"(src)
                 : "memory");
}
#define CP_COMMIT() asm volatile("cp.async.commit_group;" ::: "memory")
#define CP_WAIT0() asm volatile("cp.async.wait_group 0;" ::: "memory")

// ---------------------------------------------------------------- main ----
constexpr int SA_HALVES = 2 * MPAD * LDA;
constexpr int SB_HALVES = 2 * NTILE * LDB;
constexpr int SMEM_BYTES =
    (SA_HALVES + SB_HALVES) * 2 + (NTILE + MPAD + 16 + 4) * 4;

__global__ void __launch_bounds__(NTHREADS, 2)
dist_kernel(const float* __restrict__ pe) {
    extern __shared__ char smem_raw[];
    __nv_bfloat16* sA = (__nv_bfloat16*)smem_raw;
    __nv_bfloat16* sB = sA + SA_HALVES;
    float* sNpe = (float*)(sB + SB_HALVES);
    float* sNs = sNpe + NTILE;
    float* sRed = sNs + MPAD;
    int* sTile = (int*)(sRed + 16);

    const int tid = threadIdx.x;
    const int warp = tid >> 5, lane = tid & 31;
    const int m_base = (warp >> 2) * 16;  // 4 m-groups over M=64
    const int n_base = (warp & 3) * 32;   // 4 n-groups over N=128

    if (tid < MPAD) sNs[tid] = g_ns[tid];

    // B loader mapping (coalesced): thread's j-th load at q*16B + j*64B
    const int r0 = tid >> 2;           // 0..127
    const int q4 = tid & 3;            // 16B sub-slot
    const size_t rowOff = (size_t)r0 * D + q4 * 4;

    // A (cp.async): 8 threads per prompt row; thread copies 1 x 16B slot
    const int ra = tid >> 3;
    const int qa = tid & 7;
    const uint32_t sA_u = (uint32_t)__cvta_generic_to_shared(sA);
    const uint32_t sB_u = (uint32_t)__cvta_generic_to_shared(sB);
    const uint32_t aDst = sA_u + (uint32_t)(ra * LDA + qa * 8) * 2;
    const __nv_bfloat16* aSrc = g_B + ra * D + qa * 8;

    const uint32_t a_off =
        (uint32_t)((m_base + (lane & 15)) * LDA + (lane >> 4) * 8) * 2;
    const uint32_t b_row = (uint32_t)(n_base + ((lane >> 4) & 1) * 8 + (lane & 7));
    const uint32_t b_k = ((lane >> 3) & 1) * 8;
    const int er = lane >> 2, ec2 = (lane & 3) * 2;

    float4 v[4];
    float lsum = 0.f;

#define CPA_A(ck, buf)                                                        \
    {                                                                         \
        cp_async16(aDst + (uint32_t)((buf)*MPAD * LDA * 2),                   \
                   aSrc + (ck)*KC);                                           \
        CP_COMMIT();                                                          \
    }
#define LDG_B(ck)                                                             \
    {                                                                         \
        const float* p = rowPtr + (ck)*KC;                                    \
        _Pragma("unroll") for (int j = 0; j < 4; ++j)                         \
            v[j] = *(const float4*)(p + j * 16);                              \
    }
#define STS_B(buf)                                                            \
    {                                                                         \
        __nv_bfloat16* dst = sB + (buf)*NTILE * LDB + r0 * LDB + q4 * 4;      \
        _Pragma("unroll") for (int j = 0; j < 4; ++j) {                       \
            nacc += v[j].x * v[j].x + v[j].y * v[j].y + v[j].z * v[j].z +     \
                    v[j].w * v[j].w;                                          \
            uint2 u;                                                          \
            u.x = pack_bf2(v[j].x, v[j].y);                                   \
            u.y = pack_bf2(v[j].z, v[j].w);                                   \
            *(uint2*)(dst + j * 16) = u;                                      \
        }                                                                     \
    }
#define STEP(s, abase, bbase)                                                 \
    {                                                                         \
        uint32_t a0, a1, a2, a3;                                              \
        ldsm4(a0, a1, a2, a3, (abase) + a_off + (s)*16 * 2);                  \
        _Pragma("unroll") for (int jj = 0; jj < 2; ++jj) {                    \
            uint32_t b0, b1, b2, b3;                                          \
            uint32_t baddr =                                                  \
                (bbase) + ((b_row + jj * 16) * LDB + (s)*16 + b_k) * 2;       \
            ldsm4(b0, b1, b2, b3, baddr);                                     \
            mma16816(acc[2 * jj], a0, a1, a2, a3, b0, b1);                    \
            mma16816(acc[2 * jj + 1], a0, a1, a2, a3, b2, b3);                \
        }                                                                     \
    }

    // ================= persistent tile loop =================
    for (;;) {
        if (tid == 0) *sTile = atomicAdd(&g_tile, 1);
        __syncthreads();
        const int t = *sTile;
        if (t >= NBLK) break;

        const float* rowPtr = pe + (size_t)t * NTILE * D + rowOff;
        float nacc = 0.f;
        float acc[4][4];
#pragma unroll
        for (int j = 0; j < 4; ++j)
#pragma unroll
            for (int q = 0; q < 4; ++q) acc[j][q] = 0.f;

        // prologue: chunk 0 -> buffer 0
        CPA_A(0, 0);
        LDG_B(0);
        STS_B(0);
        CP_WAIT0();
        __syncthreads();

#pragma unroll 1
        for (int it = 0; it < NCHUNK; ++it) {
            const uint32_t abase = sA_u + (uint32_t)((it & 1) * MPAD * LDA * 2);
            const uint32_t bbase = sB_u + (uint32_t)((it & 1) * NTILE * LDB * 2);
            const bool dl = (it + 1) < NCHUNK;
            const int nb = (it + 1) & 1;

            if (dl) { LDG_B(it + 1); CPA_A(it + 1, nb); }
            STEP(0, abase, bbase);
            STEP(1, abase, bbase);
            STEP(2, abase, bbase);
            STEP(3, abase, bbase);
            if (dl) { STS_B(nb); CP_WAIT0(); }
            __syncthreads();
        }

        // |pe|^2 per row: combine the four quarter-row partials
        nacc += __shfl_xor_sync(0xffffffffu, nacc, 1);
        nacc += __shfl_xor_sync(0xffffffffu, nacc, 2);
        if ((tid & 3) == 0) sNpe[r0] = nacc;
        __syncthreads();

        // epilogue: d = sqrt(|s'|^2 + |pe|^2 - 2 dot), mask prompts >= 50
#pragma unroll
        for (int j = 0; j < 4; ++j) {
            int n = n_base + j * 8 + ec2;
            float np0 = sNpe[n], np1 = sNpe[n + 1];
            int m0 = m_base + er;
            if (m0 < NPROMPT) {
                float ns0 = sNs[m0];
                lsum += sqrtf(fmaxf(ns0 + np0 - 2.f * acc[j][0], 0.f));
                lsum += sqrtf(fmaxf(ns0 + np1 - 2.f * acc[j][1], 0.f));
            }
            int m1 = m0 + 8;
            if (m1 < NPROMPT) {
                float ns1 = sNs[m1];
                lsum += sqrtf(fmaxf(ns1 + np0 - 2.f * acc[j][2], 0.f));
                lsum += sqrtf(fmaxf(ns1 + np1 - 2.f * acc[j][3], 0.f));
            }
        }
        // next iteration's tile-fetch __syncthreads orders sNpe reuse
    }

    // ---- block reduction of lsum across all tiles this CTA processed
#pragma unroll
    for (int o = 16; o > 0; o >>= 1)
        lsum += __shfl_xor_sync(0xffffffffu, lsum, o);
    if (lane == 0) sRed[warp] = lsum;
    __syncthreads();
    if (warp == 0) {
        float sv = (lane < 16) ? sRed[lane] : 0.f;
#pragma unroll
        for (int o = 8; o > 0; o >>= 1)
            sv += __shfl_xor_sync(0xffffffffu, sv, o);
        if (lane == 0) atomicAdd(&g_acc, (double)sv);
    }
}

// -------------------------------------------------------------- finish ----
__global__ void finish_kernel(float* out) {
    out[0] = (float)(g_acc * (1.0 / ((double)NPROMPT * 197.0 * 1024.0)));
}

// -------------------------------------------------------------- launch ----
extern "C" void kernel_launch(void* const* d_in, const int* in_sizes, int n_in,
                              void* d_out, int out_size) {
    const float* src = (const float*)d_in[0];  // source_prompt [50,768]
    const float* pe = (const float*)d_in[1];   // patch_embeds [1024,197,768]
    float* out = (float*)d_out;

    cudaFuncSetAttribute(dist_kernel, cudaFuncAttributeMaxDynamicSharedMemorySize,
                         SMEM_BYTES);

    prep_kernel<<<MPAD, 256>>>(src);
    dist_kernel<<<GRID, NTHREADS, SMEM_BYTES>>>(pe);
    finish_kernel<<<1, 1>>>(out);
}